// round 14
// baseline (speedup 1.0000x reference)
#include <cuda_runtime.h>
#include <cuda_fp16.h>
#include <cstdint>

#define S_ 256
#define BB 32
#define PROW 4096            // floats per (b,s) row, planar (W*M)
#define PLANE 33554432       // elems per plane (B*S*W*M)
#define NTHR 512
#define XP 136               // Xs row stride in halves (128 + 8 pad)
#define KWP 264              // Ws row stride in halves (256 + 8 pad)

__device__ __align__(16) __half d_Wh[S_ * S_];   // diag(gain)*conn fp16 [srow][k]
__device__ float2 d_tbl[S_ * 64];                // (decay*cos, decay*sin) per (s,w)

static __device__ __forceinline__ unsigned h2u(__half2 h) {
    return ((unsigned)__half_as_ushort(__high2half(h)) << 16) |
           (unsigned)__half_as_ushort(__low2half(h));
}
static __device__ __forceinline__ void ldsm4(uint32_t* r, uint32_t a) {
    asm volatile("ldmatrix.sync.aligned.m8n8.x4.shared.b16 {%0,%1,%2,%3}, [%4];"
                 : "=r"(r[0]), "=r"(r[1]), "=r"(r[2]), "=r"(r[3]) : "r"(a));
}
static __device__ __forceinline__ void ldsm4t(uint32_t* r, uint32_t a) {
    asm volatile("ldmatrix.sync.aligned.m8n8.x4.trans.shared.b16 {%0,%1,%2,%3}, [%4];"
                 : "=r"(r[0]), "=r"(r[1]), "=r"(r[2]), "=r"(r[3]) : "r"(a));
}
static __device__ __forceinline__ void mma16816(float* c, const uint32_t* a,
                                                uint32_t b0, uint32_t b1) {
    asm volatile(
        "mma.sync.aligned.m16n8k16.row.col.f32.f16.f16.f32 "
        "{%0,%1,%2,%3}, {%4,%5,%6,%7}, {%8,%9}, {%0,%1,%2,%3};"
        : "+f"(c[0]), "+f"(c[1]), "+f"(c[2]), "+f"(c[3])
        : "r"(a[0]), "r"(a[1]), "r"(a[2]), "r"(a[3]), "r"(b0), "r"(b1));
}

// ---------------------------------------------------------------------------
__global__ void prep_kernel(const float* __restrict__ conn,
                            const float* __restrict__ gain,
                            const float* __restrict__ ww,
                            const float* __restrict__ disp) {
    int t = threadIdx.x;
    float g = gain[t];
    for (int j = 0; j < S_; j++)
        d_Wh[t * S_ + j] = __float2half(g * conn[t * S_ + j]);
    for (int i = t; i < S_ * 64; i += S_) {
        int w = i & 63;
        float phi = 0.1f * disp[w];
        float d = 0.95f * ww[i];
        d_tbl[i] = make_float2(d * cosf(phi), d * sinf(phi));
    }
}

// ---------------------------------------------------------------------------
// Fully fused 4-step kernel. CTA = (b, w), 512 threads (128-reg cap -> no
// spills). Xs fp16 panel + FULL W matrix in SMEM; zero barriers in K loop.
// 16 warps tile the 256x128 output as 8 m-stripes(x32) x 2 n-stripes(x64).
// ---------------------------------------------------------------------------
__global__ __launch_bounds__(NTHR, 1) void fused_kernel(
    const float* __restrict__ in0,   // real plane
    const float* __restrict__ in1,   // imag plane
    float* __restrict__ out,         // (2,B,S,W,M) planar
    const float* __restrict__ gain,
    const float* __restrict__ bias) {
    extern __shared__ __half sm[];
    __half* Xs = sm;                 // [256][XP]
    __half* Ws = sm + S_ * XP;       // [256][KWP]

    int tid = threadIdx.x, warp = tid >> 5, lane = tid & 31;
    int b = blockIdx.x >> 6, w = blockIdx.x & 63;
    size_t pbase = (size_t)b * ((size_t)S_ * PROW) + (size_t)w * 64;

    // ---- stage full W matrix (once, reused by all 4 steps) ----
    for (int idx = tid; idx < S_ * 32; idx += NTHR) {
        int r = idx >> 5, q = idx & 31;
        *(uint4*)(Ws + r * KWP + 8 * q) = *(const uint4*)(d_Wh + r * S_ + 8 * q);
    }

    // ---- stage Xs fp16 panel from planar input ----
    for (int idx = tid; idx < S_ * 16; idx += NTHR) {
        int k = idx >> 4, q = idx & 15;
        size_t pa = pbase + (size_t)k * PROW + 4 * q;
        float4 fr = *(const float4*)(in0 + pa);
        float4 fi = *(const float4*)(in1 + pa);
        uint4 pk = make_uint4(h2u(__floats2half2_rn(fr.x, fi.x)),
                              h2u(__floats2half2_rn(fr.y, fi.y)),
                              h2u(__floats2half2_rn(fr.z, fi.z)),
                              h2u(__floats2half2_rn(fr.w, fi.w)));
        *(uint4*)(Xs + k * XP + 8 * q) = pk;
    }

    int mstripe = (warp & 7) * 32;
    int nstripe = (warp >> 3) * 64;
    int lr = (lane & 7) + ((lane >> 3) & 1) * 8;
    int lc = (lane >> 4) * 8;
    int r4 = lane >> 2, c2 = 2 * (lane & 3);
    uint32_t sXa = (uint32_t)__cvta_generic_to_shared(Xs);
    uint32_t sWa = (uint32_t)__cvta_generic_to_shared(Ws);
    uint32_t bBase = sXa + (uint32_t)((lr * XP + nstripe + lc) * 2);
    uint32_t a0Base = sWa + (uint32_t)(((mstripe + lr) * KWP + lc) * 2);
    uint32_t a1Base = a0Base + (uint32_t)(16 * KWP * 2);

    // ---- init state: raw field into accumulators (exact fp32) ----
    float acc[2][8][4];
    #pragma unroll
    for (int mi = 0; mi < 2; mi++)
        #pragma unroll
        for (int h = 0; h < 2; h++) {
            int srow = mstripe + mi * 16 + h * 8 + r4;
            #pragma unroll
            for (int nj = 0; nj < 8; nj++) {
                int nsc = nstripe + nj * 8 + c2;
                size_t pa = pbase + (size_t)srow * PROW + (nsc >> 1);
                acc[mi][nj][2 * h]     = __ldg(in0 + pa);
                acc[mi][nj][2 * h + 1] = __ldg(in1 + pa);
            }
        }
    __syncthreads();   // Ws + Xs staged

    #pragma unroll 1
    for (int step = 0; step < 4; step++) {
        // ---- acc-init: acc = g*self + bias(real) ----
        #pragma unroll
        for (int mi = 0; mi < 2; mi++)
            #pragma unroll
            for (int h = 0; h < 2; h++) {
                int srow = mstripe + mi * 16 + h * 8 + r4;
                float g = __ldg(gain + srow), bv = __ldg(bias + srow);
                #pragma unroll
                for (int nj = 0; nj < 8; nj++) {
                    acc[mi][nj][2 * h]     = fmaf(g, acc[mi][nj][2 * h], bv);
                    acc[mi][nj][2 * h + 1] = g * acc[mi][nj][2 * h + 1];
                }
            }

        // ---- K loop: acc += (g*conn) @ X ; no barriers ----
        #pragma unroll
        for (int kb = 0; kb < 16; kb++) {
            uint32_t koff = (uint32_t)(kb * 16 * 2);
            uint32_t xoff = (uint32_t)(kb * 16 * XP * 2);
            uint32_t ra0[4], ra1[4];
            ldsm4(ra0, a0Base + koff);
            ldsm4(ra1, a1Base + koff);
            #pragma unroll
            for (int q = 0; q < 4; q++) {        // 4 n16 groups = 64 cols
                uint32_t rb[4];
                ldsm4t(rb, bBase + xoff + (uint32_t)(q * 32));
                mma16816(acc[0][2 * q],     ra0, rb[0], rb[1]);
                mma16816(acc[0][2 * q + 1], ra0, rb[2], rb[3]);
                mma16816(acc[1][2 * q],     ra1, rb[0], rb[1]);
                mma16816(acc[1][2 * q + 1], ra1, rb[2], rb[3]);
            }
        }
        __syncthreads();   // all Xs reads done before epilogue rewrites

        // ---- epilogue: saturate + rotate; state stays in acc ----
        #pragma unroll
        for (int mi = 0; mi < 2; mi++)
            #pragma unroll
            for (int h = 0; h < 2; h++) {
                int srow = mstripe + mi * 16 + h * 8 + r4;
                float2 dcs = __ldg(&d_tbl[(srow << 6) + w]);
                #pragma unroll
                for (int nj = 0; nj < 8; nj++) {
                    int nsc = nstripe + nj * 8 + c2;
                    float fre = acc[mi][nj][2 * h];
                    float fim = acc[mi][nj][2 * h + 1];
                    float inten = fmaf(fre, fre, fim * fim);
                    float sc = __frcp_rn(fmaf(0.5f, inten, 1.0f));
                    fre *= sc; fim *= sc;
                    float ore = fmaf(dcs.x, fre, -dcs.y * fim);
                    float oim = fmaf(dcs.y, fre,  dcs.x * fim);
                    acc[mi][nj][2 * h]     = ore;
                    acc[mi][nj][2 * h + 1] = oim;
                    if (step < 3) {
                        *(__half2*)(Xs + srow * XP + nsc) =
                            __floats2half2_rn(ore, oim);
                    } else {
                        size_t pa = pbase + (size_t)srow * PROW + (nsc >> 1);
                        out[pa] = ore;
                        out[(size_t)PLANE + pa] = oim;
                    }
                }
            }
        if (step < 3) __syncthreads();   // Xs rewritten before next step reads
    }
}

// ---------------------------------------------------------------------------
extern "C" void kernel_launch(void* const* d_in, const int* in_sizes, int n_in,
                              void* d_out, int out_size) {
    const float* fr   = (const float*)d_in[0];
    const float* fi   = (const float*)d_in[1];
    const float* conn = (const float*)d_in[2];
    const float* gain = (const float*)d_in[3];
    const float* bias = (const float*)d_in[4];
    const float* ww   = (const float*)d_in[5];
    const float* disp = (const float*)d_in[6];
    float* out = (float*)d_out;

    const int smem = (S_ * XP + S_ * KWP) * 2;   // 204,800 B
    cudaFuncSetAttribute(fused_kernel,
                         cudaFuncAttributeMaxDynamicSharedMemorySize, smem);

    prep_kernel<<<1, 256>>>(conn, gain, ww, disp);
    fused_kernel<<<BB * 64, NTHR, smem>>>(fr, fi, out, gain, bias);
}

// round 15
// speedup vs baseline: 1.0194x; 1.0194x over previous
#include <cuda_runtime.h>
#include <cuda_fp16.h>
#include <cstdint>

#define S_ 256
#define BB 32
#define PROW 4096            // floats per (b,s) row, planar (W*M)
#define PLANE 33554432       // elems per plane (B*S*W*M)
#define NTHR 1024
#define XSP 72               // Xs row stride in halves (64 + 8 pad)
#define KWP 264              // Ws row stride in halves (256 + 8 pad)

__device__ __align__(16) __half d_Wh[S_ * S_];   // diag(gain)*conn fp16 [srow][k]
__device__ float2 d_tbl[S_ * 64];                // (decay*cos, decay*sin) per (s,w)

static __device__ __forceinline__ unsigned h2u(__half2 h) {
    return ((unsigned)__half_as_ushort(__high2half(h)) << 16) |
           (unsigned)__half_as_ushort(__low2half(h));
}
static __device__ __forceinline__ void ldsm4(uint32_t* r, uint32_t a) {
    asm volatile("ldmatrix.sync.aligned.m8n8.x4.shared.b16 {%0,%1,%2,%3}, [%4];"
                 : "=r"(r[0]), "=r"(r[1]), "=r"(r[2]), "=r"(r[3]) : "r"(a));
}
static __device__ __forceinline__ void ldsm4t(uint32_t* r, uint32_t a) {
    asm volatile("ldmatrix.sync.aligned.m8n8.x4.trans.shared.b16 {%0,%1,%2,%3}, [%4];"
                 : "=r"(r[0]), "=r"(r[1]), "=r"(r[2]), "=r"(r[3]) : "r"(a));
}
static __device__ __forceinline__ void mma16816(float* c, const uint32_t* a,
                                                uint32_t b0, uint32_t b1) {
    asm volatile(
        "mma.sync.aligned.m16n8k16.row.col.f32.f16.f16.f32 "
        "{%0,%1,%2,%3}, {%4,%5,%6,%7}, {%8,%9}, {%0,%1,%2,%3};"
        : "+f"(c[0]), "+f"(c[1]), "+f"(c[2]), "+f"(c[3])
        : "r"(a[0]), "r"(a[1]), "r"(a[2]), "r"(a[3]), "r"(b0), "r"(b1));
}

// ---------------------------------------------------------------------------
__global__ void prep_kernel(const float* __restrict__ conn,
                            const float* __restrict__ gain,
                            const float* __restrict__ ww,
                            const float* __restrict__ disp) {
    int t = threadIdx.x;
    float g = gain[t];
    for (int j = 0; j < S_; j++)
        d_Wh[t * S_ + j] = __float2half(g * conn[t * S_ + j]);
    for (int i = t; i < S_ * 64; i += S_) {
        int w = i & 63;
        float phi = 0.1f * disp[w];
        float d = 0.95f * ww[i];
        d_tbl[i] = make_float2(d * cosf(phi), d * sinf(phi));
    }
}

// ---------------------------------------------------------------------------
// Fully fused 4-step kernel. CTA = (b, w, col-half): 64 scalar cols.
// Xs fp16 panel [256][64] + FULL W in SMEM (172KB); zero-barrier K loop.
// 32 warps tile the 256x64 output as 8 m-stripes(x32) x 4 n-stripes(x16):
// acc = 16 regs/thread -> ~20 regs of prefetch slack per warp at 1024 thr.
// ---------------------------------------------------------------------------
__global__ __launch_bounds__(NTHR, 1) void fused_kernel(
    const float* __restrict__ in0,   // real plane
    const float* __restrict__ in1,   // imag plane
    float* __restrict__ out,         // (2,B,S,W,M) planar
    const float* __restrict__ gain,
    const float* __restrict__ bias) {
    extern __shared__ __half sm[];
    __half* Xs = sm;                 // [256][XSP]
    __half* Ws = sm + S_ * XSP;      // [256][KWP]

    int tid = threadIdx.x, warp = tid >> 5, lane = tid & 31;
    int bid = blockIdx.x;
    int b = bid >> 7;
    int w = (bid >> 1) & 63;
    int ch = bid & 1;                // column half
    size_t pbase = (size_t)b * ((size_t)S_ * PROW) + (size_t)w * 64 + ch * 32;

    // ---- stage full W matrix (once, reused by all 4 steps) ----
    for (int idx = tid; idx < S_ * 32; idx += NTHR) {
        int r = idx >> 5, q = idx & 31;
        *(uint4*)(Ws + r * KWP + 8 * q) = *(const uint4*)(d_Wh + r * S_ + 8 * q);
    }

    // ---- stage Xs fp16 panel (64 scalar cols) from planar input ----
    for (int idx = tid; idx < S_ * 8; idx += NTHR) {
        int k = idx >> 3, q = idx & 7;
        size_t pa = pbase + (size_t)k * PROW + 4 * q;
        float4 fr = *(const float4*)(in0 + pa);
        float4 fi = *(const float4*)(in1 + pa);
        uint4 pk = make_uint4(h2u(__floats2half2_rn(fr.x, fi.x)),
                              h2u(__floats2half2_rn(fr.y, fi.y)),
                              h2u(__floats2half2_rn(fr.z, fi.z)),
                              h2u(__floats2half2_rn(fr.w, fi.w)));
        *(uint4*)(Xs + k * XSP + 8 * q) = pk;
    }

    int mstripe = (warp & 7) * 32;
    int nstripe = (warp >> 3) * 16;
    int lr = (lane & 7) + ((lane >> 3) & 1) * 8;
    int lc = (lane >> 4) * 8;
    int r4 = lane >> 2, c2 = 2 * (lane & 3);
    uint32_t sXa = (uint32_t)__cvta_generic_to_shared(Xs);
    uint32_t sWa = (uint32_t)__cvta_generic_to_shared(Ws);
    uint32_t bBase = sXa + (uint32_t)((lr * XSP + nstripe + lc) * 2);
    uint32_t a0Base = sWa + (uint32_t)(((mstripe + lr) * KWP + lc) * 2);
    uint32_t a1Base = a0Base + (uint32_t)(16 * KWP * 2);

    // ---- init state: raw field into accumulators (exact fp32) ----
    float acc[2][2][4];
    #pragma unroll
    for (int mi = 0; mi < 2; mi++)
        #pragma unroll
        for (int h = 0; h < 2; h++) {
            int srow = mstripe + mi * 16 + h * 8 + r4;
            #pragma unroll
            for (int nj = 0; nj < 2; nj++) {
                int nsc = nstripe + nj * 8 + c2;
                size_t pa = pbase + (size_t)srow * PROW + (nsc >> 1);
                acc[mi][nj][2 * h]     = __ldg(in0 + pa);
                acc[mi][nj][2 * h + 1] = __ldg(in1 + pa);
            }
        }
    __syncthreads();   // Ws + Xs staged

    #pragma unroll 1
    for (int step = 0; step < 4; step++) {
        // ---- acc-init: acc = g*self + bias(real) ----
        #pragma unroll
        for (int mi = 0; mi < 2; mi++)
            #pragma unroll
            for (int h = 0; h < 2; h++) {
                int srow = mstripe + mi * 16 + h * 8 + r4;
                float g = __ldg(gain + srow), bv = __ldg(bias + srow);
                #pragma unroll
                for (int nj = 0; nj < 2; nj++) {
                    acc[mi][nj][2 * h]     = fmaf(g, acc[mi][nj][2 * h], bv);
                    acc[mi][nj][2 * h + 1] = g * acc[mi][nj][2 * h + 1];
                }
            }

        // ---- K loop: acc += (g*conn) @ X ; no barriers ----
        #pragma unroll
        for (int kb = 0; kb < 16; kb++) {
            uint32_t koff = (uint32_t)(kb * 16 * 2);
            uint32_t ra0[4], ra1[4], rb[4];
            ldsm4(ra0, a0Base + koff);
            ldsm4(ra1, a1Base + koff);
            ldsm4t(rb, bBase + (uint32_t)(kb * 16 * XSP * 2));
            mma16816(acc[0][0], ra0, rb[0], rb[1]);
            mma16816(acc[0][1], ra0, rb[2], rb[3]);
            mma16816(acc[1][0], ra1, rb[0], rb[1]);
            mma16816(acc[1][1], ra1, rb[2], rb[3]);
        }
        __syncthreads();   // all Xs reads done before epilogue rewrites

        // ---- epilogue: saturate + rotate; state stays in acc ----
        #pragma unroll
        for (int mi = 0; mi < 2; mi++)
            #pragma unroll
            for (int h = 0; h < 2; h++) {
                int srow = mstripe + mi * 16 + h * 8 + r4;
                float2 dcs = __ldg(&d_tbl[(srow << 6) + w]);
                #pragma unroll
                for (int nj = 0; nj < 2; nj++) {
                    int nsc = nstripe + nj * 8 + c2;
                    float fre = acc[mi][nj][2 * h];
                    float fim = acc[mi][nj][2 * h + 1];
                    float inten = fmaf(fre, fre, fim * fim);
                    float sc = __frcp_rn(fmaf(0.5f, inten, 1.0f));
                    fre *= sc; fim *= sc;
                    float ore = fmaf(dcs.x, fre, -dcs.y * fim);
                    float oim = fmaf(dcs.y, fre,  dcs.x * fim);
                    acc[mi][nj][2 * h]     = ore;
                    acc[mi][nj][2 * h + 1] = oim;
                    if (step < 3) {
                        *(__half2*)(Xs + srow * XSP + nsc) =
                            __floats2half2_rn(ore, oim);
                    } else {
                        size_t pa = pbase + (size_t)srow * PROW + (nsc >> 1);
                        out[pa] = ore;
                        out[(size_t)PLANE + pa] = oim;
                    }
                }
            }
        if (step < 3) __syncthreads();   // Xs rewritten before next step reads
    }
}

// ---------------------------------------------------------------------------
extern "C" void kernel_launch(void* const* d_in, const int* in_sizes, int n_in,
                              void* d_out, int out_size) {
    const float* fr   = (const float*)d_in[0];
    const float* fi   = (const float*)d_in[1];
    const float* conn = (const float*)d_in[2];
    const float* gain = (const float*)d_in[3];
    const float* bias = (const float*)d_in[4];
    const float* ww   = (const float*)d_in[5];
    const float* disp = (const float*)d_in[6];
    float* out = (float*)d_out;

    const int smem = (S_ * XSP + S_ * KWP) * 2;   // 36,864 + 135,168 = 172,032 B
    cudaFuncSetAttribute(fused_kernel,
                         cudaFuncAttributeMaxDynamicSharedMemorySize, smem);

    prep_kernel<<<1, 256>>>(conn, gain, ww, disp);
    fused_kernel<<<BB * 64 * 2, NTHR, smem>>>(fr, fi, out, gain, bias);
}

// round 16
// speedup vs baseline: 1.0390x; 1.0192x over previous
#include <cuda_runtime.h>
#include <cuda_fp16.h>
#include <cstdint>

#define S_ 256
#define BB 32
#define PROW 4096            // floats per (b,s) row, planar (W*M)
#define PLANE 33554432       // elems per plane (B*S*W*M)
#define NTHR 512
#define XSP 72               // Xs row stride in halves (64 + 8 pad)

__device__ __align__(16) __half d_Wh[S_ * S_];   // diag(gain)*conn fp16 [srow][k]
__device__ float2 d_tbl[S_ * 64];                // (decay*cos, decay*sin) per (s,w)

static __device__ __forceinline__ unsigned h2u(__half2 h) {
    return ((unsigned)__half_as_ushort(__high2half(h)) << 16) |
           (unsigned)__half_as_ushort(__low2half(h));
}
static __device__ __forceinline__ void ldsm4t(uint32_t* r, uint32_t a) {
    asm volatile("ldmatrix.sync.aligned.m8n8.x4.trans.shared.b16 {%0,%1,%2,%3}, [%4];"
                 : "=r"(r[0]), "=r"(r[1]), "=r"(r[2]), "=r"(r[3]) : "r"(a));
}
static __device__ __forceinline__ void mma16816(float* c, const uint32_t* a,
                                                uint32_t b0, uint32_t b1) {
    asm volatile(
        "mma.sync.aligned.m16n8k16.row.col.f32.f16.f16.f32 "
        "{%0,%1,%2,%3}, {%4,%5,%6,%7}, {%8,%9}, {%0,%1,%2,%3};"
        : "+f"(c[0]), "+f"(c[1]), "+f"(c[2]), "+f"(c[3])
        : "r"(a[0]), "r"(a[1]), "r"(a[2]), "r"(a[3]), "r"(b0), "r"(b1));
}

// ---------------------------------------------------------------------------
__global__ void prep_kernel(const float* __restrict__ conn,
                            const float* __restrict__ gain,
                            const float* __restrict__ ww,
                            const float* __restrict__ disp) {
    int t = threadIdx.x;
    float g = gain[t];
    for (int j = 0; j < S_; j++)
        d_Wh[t * S_ + j] = __float2half(g * conn[t * S_ + j]);
    for (int i = t; i < S_ * 64; i += S_) {
        int w = i & 63;
        float phi = 0.1f * disp[w];
        float d = 0.95f * ww[i];
        d_tbl[i] = make_float2(d * cosf(phi), d * sinf(phi));
    }
}

// ---------------------------------------------------------------------------
// Fully fused 4-step kernel, A-fragments persistent in registers.
// CTA = (b, w, col-half): 256 rows x 64 scalar cols. 16 warps, warp-tile
// m16 x n64. W (constant across steps/CTAs) lives entirely in registers:
// raA[16][4] loaded once via LDG in mma A-frag layout. K loop = B-ldsm + mma
// only, zero barriers. Xs fp16 panel (37KB) is the sole smem use.
// ---------------------------------------------------------------------------
__global__ __launch_bounds__(NTHR, 1) void fused_kernel(
    const float* __restrict__ in0,   // real plane
    const float* __restrict__ in1,   // imag plane
    float* __restrict__ out,         // (2,B,S,W,M) planar
    const float* __restrict__ gain,
    const float* __restrict__ bias) {
    extern __shared__ __half Xs[];   // [256][XSP]

    int tid = threadIdx.x, warp = tid >> 5, lane = tid & 31;
    int bid = blockIdx.x;
    int b = bid >> 7;
    int w = (bid >> 1) & 63;
    int ch = bid & 1;                // column half
    size_t pbase = (size_t)b * ((size_t)S_ * PROW) + (size_t)w * 64 + ch * 32;

    // ---- stage Xs fp16 panel (64 scalar cols) from planar input ----
    for (int idx = tid; idx < S_ * 8; idx += NTHR) {
        int k = idx >> 3, q = idx & 7;
        size_t pa = pbase + (size_t)k * PROW + 4 * q;
        float4 fr = *(const float4*)(in0 + pa);
        float4 fi = *(const float4*)(in1 + pa);
        uint4 pk = make_uint4(h2u(__floats2half2_rn(fr.x, fi.x)),
                              h2u(__floats2half2_rn(fr.y, fi.y)),
                              h2u(__floats2half2_rn(fr.z, fi.z)),
                              h2u(__floats2half2_rn(fr.w, fi.w)));
        *(uint4*)(Xs + k * XSP + 8 * q) = pk;
    }

    int mrow0 = warp * 16;           // this warp's 16 output rows
    int lr = (lane & 7) + ((lane >> 3) & 1) * 8;
    int lc = (lane >> 4) * 8;
    int r4 = lane >> 2, c2 = 2 * (lane & 3);
    uint32_t sXa = (uint32_t)__cvta_generic_to_shared(Xs);
    uint32_t bBase = sXa + (uint32_t)((lr * XSP + lc) * 2);

    // ---- persistent A-fragments: W rows [mrow0, mrow0+16), all K=256 ----
    // mma m16n8k16 A-frag layout: a0=(m=lane/4, k=2(lane%4)), a1=+8m,
    // a2=+8k, a3=+8m+8k. Loaded once; reused by all 4 steps.
    uint32_t raA[16][4];
    {
        const __half* p0 = d_Wh + (size_t)(mrow0 + r4) * S_ + c2;
        #pragma unroll
        for (int kb = 0; kb < 16; kb++) {
            const __half* p = p0 + kb * 16;
            raA[kb][0] = *(const uint32_t*)p;
            raA[kb][1] = *(const uint32_t*)(p + 8 * S_);
            raA[kb][2] = *(const uint32_t*)(p + 8);
            raA[kb][3] = *(const uint32_t*)(p + 8 * S_ + 8);
        }
    }

    // ---- init state: raw field into accumulators (exact fp32) ----
    float acc[8][4];
    #pragma unroll
    for (int h = 0; h < 2; h++) {
        int srow = mrow0 + h * 8 + r4;
        #pragma unroll
        for (int nj = 0; nj < 8; nj++) {
            int nsc = nj * 8 + c2;
            size_t pa = pbase + (size_t)srow * PROW + (nsc >> 1);
            acc[nj][2 * h]     = __ldg(in0 + pa);
            acc[nj][2 * h + 1] = __ldg(in1 + pa);
        }
    }
    __syncthreads();   // Xs staged

    #pragma unroll 1
    for (int step = 0; step < 4; step++) {
        // ---- acc-init: acc = g*self + bias(real) ----
        #pragma unroll
        for (int h = 0; h < 2; h++) {
            int srow = mrow0 + h * 8 + r4;
            float g = __ldg(gain + srow), bv = __ldg(bias + srow);
            #pragma unroll
            for (int nj = 0; nj < 8; nj++) {
                acc[nj][2 * h]     = fmaf(g, acc[nj][2 * h], bv);
                acc[nj][2 * h + 1] = g * acc[nj][2 * h + 1];
            }
        }

        // ---- K loop: acc += (g*conn) @ X ; A from regs, no barriers ----
        #pragma unroll
        for (int kb = 0; kb < 16; kb++) {
            uint32_t xoff = (uint32_t)(kb * 16 * XSP * 2);
            #pragma unroll
            for (int q = 0; q < 4; q++) {        // 4 n16 groups = 64 cols
                uint32_t rb[4];
                ldsm4t(rb, bBase + xoff + (uint32_t)(q * 32));
                mma16816(acc[2 * q],     raA[kb], rb[0], rb[1]);
                mma16816(acc[2 * q + 1], raA[kb], rb[2], rb[3]);
            }
        }
        __syncthreads();   // all Xs reads done before epilogue rewrites

        // ---- epilogue: saturate + rotate; state stays in acc ----
        #pragma unroll
        for (int h = 0; h < 2; h++) {
            int srow = mrow0 + h * 8 + r4;
            float2 dcs = __ldg(&d_tbl[(srow << 6) + w]);
            #pragma unroll
            for (int nj = 0; nj < 8; nj++) {
                int nsc = nj * 8 + c2;
                float fre = acc[nj][2 * h];
                float fim = acc[nj][2 * h + 1];
                float inten = fmaf(fre, fre, fim * fim);
                float sc = __frcp_rn(fmaf(0.5f, inten, 1.0f));
                fre *= sc; fim *= sc;
                float ore = fmaf(dcs.x, fre, -dcs.y * fim);
                float oim = fmaf(dcs.y, fre,  dcs.x * fim);
                acc[nj][2 * h]     = ore;
                acc[nj][2 * h + 1] = oim;
                if (step < 3) {
                    *(__half2*)(Xs + srow * XSP + nsc) =
                        __floats2half2_rn(ore, oim);
                } else {
                    size_t pa = pbase + (size_t)srow * PROW + (nsc >> 1);
                    out[pa] = ore;
                    out[(size_t)PLANE + pa] = oim;
                }
            }
        }
        if (step < 3) __syncthreads();   // Xs rewritten before next step reads
    }
}

// ---------------------------------------------------------------------------
extern "C" void kernel_launch(void* const* d_in, const int* in_sizes, int n_in,
                              void* d_out, int out_size) {
    const float* fr   = (const float*)d_in[0];
    const float* fi   = (const float*)d_in[1];
    const float* conn = (const float*)d_in[2];
    const float* gain = (const float*)d_in[3];
    const float* bias = (const float*)d_in[4];
    const float* ww   = (const float*)d_in[5];
    const float* disp = (const float*)d_in[6];
    float* out = (float*)d_out;

    const int smem = S_ * XSP * 2;   // 36,864 B
    cudaFuncSetAttribute(fused_kernel,
                         cudaFuncAttributeMaxDynamicSharedMemorySize, smem);

    prep_kernel<<<1, 256>>>(conn, gain, ww, disp);
    fused_kernel<<<BB * 64 * 2, NTHR, smem>>>(fr, fi, out, gain, bias);
}